// round 10
// baseline (speedup 1.0000x reference)
#include <cuda_runtime.h>
#include <cstdint>

#define KK 16
#define BB 512
#define NP 4096
#define EPSF 1e-13f
#define TOLF 1.001e-5f       // np.isclose to 1.0: rtol(1e-5)*1.0 + atol(1e-8)
#define LOG2E 1.4426950408889634f

// labels split into 4 planes; plane p holds concepts 4p..4p+3 (one byte each).
// train point n lives at plane index (n&3)*1024 + (n>>2);
// beran thread t (owning n = 4t..4t+3) reads g_pk[p][j*1024 + t] -> coalesced.
__device__ unsigned g_pk[4][NP];

__global__ void pack_labels_kernel(const int* __restrict__ c_in) {
    int t = blockIdx.x * blockDim.x + threadIdx.x;
    if (t < NP) {
        const int4* p = (const int4*)(c_in + t * KK);
        int idx = (t & 3) * 1024 + (t >> 2);
        #pragma unroll
        for (int q = 0; q < 4; q++) {
            int4 a = p[q];
            g_pk[q][idx] = (a.x & 255u) | ((a.y & 255u) << 8)
                         | ((a.z & 255u) << 16) | ((a.w & 255u) << 24);
        }
    }
}

// Each block: 1024 threads, TWO samples (b0, b0+1), 4 train points per thread.
__global__ __launch_bounds__(1024, 2) void beran_kernel(
    const float* __restrict__ delta,
    const float* __restrict__ c_p,
    const float* __restrict__ bwp,
    float* __restrict__ out)
{
    __shared__ float s_score[2 * KK * 32];  // 4 KB: [h][k][v]
    __shared__ float wsA[32], wsB[32];

    const int tid  = threadIdx.x;
    const int lane = tid & 31;
    const int wid  = tid >> 5;          // 0..31
    const int b0   = blockIdx.x * 2;
    const unsigned FULL = 0xFFFFFFFFu;

    // ---- Phase A: 32 softmax tasks, one per warp: h = wid>>4, k = wid&15 ----
    {
        int h = wid >> 4, k = wid & 15;
        float x = c_p[(k * BB + b0 + h) * 32 + lane];
        float m = x;
        #pragma unroll
        for (int d = 16; d; d >>= 1) m = fmaxf(m, __shfl_xor_sync(FULL, m, d));
        float e = __expf(x - m);
        float s = e;
        #pragma unroll
        for (int d = 16; d; d >>= 1) s += __shfl_xor_sync(FULL, s, d);
        float p = __fdividef(e, s);
        float ssq = p * p;
        #pragma unroll
        for (int d = 16; d; d >>= 1) ssq += __shfl_xor_sync(FULL, ssq, d);
        s_score[h * 512 + k * 32 + lane] = ssq - 2.0f * p + 1.0f;
    }

    // early delta load: latency hides under Phase A tail + Phase B
    float4 dv = ((const float4*)(delta))[tid];   // delta[4t..4t+3]

    __syncthreads();   // barrier 1

    const float bw   = fminf(fmaxf(bwp[0], 0.1f), 10.0f);
    const float nib2 = -LOG2E / bw;     // base-2 exponent scale

    // ---- Phase B: gather in 4 quarter-passes (4 concepts at a time) ----
    float oa[4] = {0, 0, 0, 0}, ob[4] = {0, 0, 0, 0};
    #pragma unroll
    for (int q = 0; q < 4; q++) {
        float srA[4], srB[4];
        #pragma unroll
        for (int kk = 0; kk < 4; kk++) {
            srA[kk] = s_score[(q * 4 + kk) * 32 + lane];
            srB[kk] = s_score[512 + (q * 4 + kk) * 32 + lane];
        }
        #pragma unroll
        for (int j = 0; j < 4; j++) {
            unsigned pk = g_pk[q][j * 1024 + tid];
            int i0 = (int)pk, i1 = (int)(pk >> 8), i2 = (int)(pk >> 16), i3 = (int)(pk >> 24);
            float ma = oa[j], mb = ob[j];
            ma += __shfl_sync(FULL, srA[0], i0); mb += __shfl_sync(FULL, srB[0], i0);
            ma += __shfl_sync(FULL, srA[1], i1); mb += __shfl_sync(FULL, srB[1], i1);
            ma += __shfl_sync(FULL, srA[2], i2); mb += __shfl_sync(FULL, srB[2], i2);
            ma += __shfl_sync(FULL, srA[3], i3); mb += __shfl_sync(FULL, srB[3], i3);
            oa[j] = ma; ob[j] = mb;
        }
    }
    #pragma unroll
    for (int j = 0; j < 4; j++) {
        oa[j] = exp2f(oa[j] * nib2);    // w values
        ob[j] = exp2f(ob[j] * nib2);
    }

    // ---- Phase C: scan #1 (cumsum of w) ----
    #pragma unroll
    for (int j = 1; j < 4; j++) { oa[j] += oa[j - 1]; ob[j] += ob[j - 1]; }

    float totA = oa[3], totB = ob[3];
    float tiA = totA, tiB = totB;
    #pragma unroll
    for (int d = 1; d < 32; d <<= 1) {
        float ua = __shfl_up_sync(FULL, tiA, d);
        float ub = __shfl_up_sync(FULL, tiB, d);
        if (lane >= d) { tiA += ua; tiB += ub; }
    }
    if (lane == 31) { wsA[wid] = tiA; wsB[wid] = tiB; }
    __syncthreads();   // barrier 2

    // redundant partial-scan: every warp scans the 32 partials itself
    float off1A, off1B, sA, sB;
    {
        float vA = wsA[lane], vB = wsB[lane];
        float viA = vA, viB = vB;
        #pragma unroll
        for (int d = 1; d < 32; d <<= 1) {
            float uA = __shfl_up_sync(FULL, viA, d);
            float uB = __shfl_up_sync(FULL, viB, d);
            if (lane >= d) { viA += uA; viB += uB; }
        }
        float eA = __shfl_sync(FULL, viA, wid - 1);   // inclusive prefix at wid-1
        float eB = __shfl_sync(FULL, viB, wid - 1);   // (wid-1 wraps to 31 for wid=0; masked below)
        if (wid == 0) { eA = 0.0f; eB = 0.0f; }
        sA = __shfl_sync(FULL, viA, 31);
        sB = __shfl_sync(FULL, viB, 31);
        off1A = eA + (tiA - totA);
        off1B = eB + (tiB - totB);
    }
    const float tolA = (sA < EPSF) ? 3.0e38f : TOLF * sA;
    const float tolB = (sB < EPSF) ? 3.0e38f : TOLF * sB;

    // ---- Phase D: xi via log-chain: xi_j = L_{j-1} - L_j, L = log2(residual) ----
    float tot2A = 0.0f, tot2B = 0.0f;
    {
        float tpA = sA - off1A, tpB = sB - off1B;
        float LA = __log2f(tpA), LB = __log2f(tpB);
        #pragma unroll
        for (int j = 0; j < 4; j++) {
            float dl = (j == 0) ? dv.x : (j == 1) ? dv.y : (j == 2) ? dv.z : dv.w;
            float tA = sA - (off1A + oa[j]);
            float tB = sB - (off1B + ob[j]);
            float LnA = __log2f(tA), LnB = __log2f(tB);
            bool badA = (fabsf(tA) <= tolA) || (fabsf(tpA) <= tolA);
            bool badB = (fabsf(tB) <= tolB) || (fabsf(tpB) <= tolB);
            float xiA = badA ? 0.0f : (LA - LnA);
            float xiB = badB ? 0.0f : (LB - LnB);
            float vA = dl * xiA, vB = dl * xiB;
            tot2A += vA; tot2B += vB;
            oa[j] = vA; ob[j] = vB;       // o[] now delta*xi (log2 units)
            tpA = tA; tpB = tB; LA = LnA; LB = LnB;
        }
    }
    #pragma unroll
    for (int j = 1; j < 4; j++) { oa[j] += oa[j - 1]; ob[j] += ob[j - 1]; }

    // ---- Phase E: scan #2 (hazards, log2 units) ----
    float ti2A = tot2A, ti2B = tot2B;
    #pragma unroll
    for (int d = 1; d < 32; d <<= 1) {
        float ua = __shfl_up_sync(FULL, ti2A, d);
        float ub = __shfl_up_sync(FULL, ti2B, d);
        if (lane >= d) { ti2A += ua; ti2B += ub; }
    }
    __syncthreads();   // barrier 3: all redundant scan-1 reads of wsA/wsB done
    if (lane == 31) { wsA[wid] = ti2A; wsB[wid] = ti2B; }
    __syncthreads();   // barrier 4

    float off2A, off2B, g2A, g2B;
    {
        float vA = wsA[lane], vB = wsB[lane];
        float viA = vA, viB = vB;
        #pragma unroll
        for (int d = 1; d < 32; d <<= 1) {
            float uA = __shfl_up_sync(FULL, viA, d);
            float uB = __shfl_up_sync(FULL, viB, d);
            if (lane >= d) { viA += uA; viB += uB; }
        }
        float eA = __shfl_sync(FULL, viA, wid - 1);
        float eB = __shfl_sync(FULL, viB, wid - 1);
        if (wid == 0) { eA = 0.0f; eB = 0.0f; }
        g2A = __shfl_sync(FULL, viA, 31);
        g2B = __shfl_sync(FULL, viB, 31);
        off2A = eA + (ti2A - tot2A);
        off2B = eB + (ti2B - tot2B);
    }

    // s2 telescopes: sum(surv_steps) = 1 - surv[N-1]; surv = exp2(-hz2)
    const float s2A = 1.0f - exp2f(-g2A);
    const float s2B = 1.0f - exp2f(-g2B);
    const float inv2A = (s2A < EPSF) ? 0.0f : 1.0f / s2A;
    const float inv2B = (s2B < EPSF) ? 0.0f : 1.0f / s2B;
    float prevA = (tid == 0) ? 1.0f : exp2f(-off2A);
    float prevB = (tid == 0) ? 1.0f : exp2f(-off2B);

    // ---- Phase F: surv (write), then steps in place ----
    #pragma unroll
    for (int j = 0; j < 4; j++) {
        oa[j] = exp2f(-(oa[j] + off2A));
        ob[j] = exp2f(-(ob[j] + off2B));
    }
    {
        float4* opA = (float4*)(out + (size_t)b0 * NP) + tid;
        float4* opB = (float4*)(out + (size_t)(b0 + 1) * NP) + tid;
        opA[0] = make_float4(oa[0], oa[1], oa[2], oa[3]);
        opB[0] = make_float4(ob[0], ob[1], ob[2], ob[3]);
    }
    #pragma unroll
    for (int j = 0; j < 4; j++) {
        float sa = oa[j], sb = ob[j];
        oa[j] = (prevA - sa) * inv2A;
        ob[j] = (prevB - sb) * inv2B;
        prevA = sa; prevB = sb;
    }
    {
        float4* opA = (float4*)(out + (size_t)BB * NP + (size_t)b0 * NP) + tid;
        float4* opB = (float4*)(out + (size_t)BB * NP + (size_t)(b0 + 1) * NP) + tid;
        opA[0] = make_float4(oa[0], oa[1], oa[2], oa[3]);
        opB[0] = make_float4(ob[0], ob[1], ob[2], ob[3]);
    }
}

extern "C" void kernel_launch(void* const* d_in, const int* in_sizes, int n_in,
                              void* d_out, int out_size) {
    const int*   c_in  = (const int*)d_in[0];
    const float* delta = (const float*)d_in[1];
    const float* c_p   = (const float*)d_in[2];
    const float* bwp   = (const float*)d_in[3];
    float* out = (float*)d_out;

    pack_labels_kernel<<<32, 128>>>(c_in);
    beran_kernel<<<BB / 2, 1024>>>(delta, c_p, bwp, out);
}

// round 11
// speedup vs baseline: 1.1196x; 1.1196x over previous
#include <cuda_runtime.h>
#include <cstdint>

#define KK 16
#define BB 512
#define NP 4096
#define EPSF 1e-13f
#define TOLF 1.001e-5f       // np.isclose to 1.0: rtol(1e-5)*1.0 + atol(1e-8)
#define LOG2E 1.4426950408889634f
#define QSCALE 2047.0f       // fixed-point scale; 16*2*2047 = 65504 < 2^16 (no carry)

// labels split into 4 planes; plane p holds concepts 4p..4p+3 (one byte each).
// train point n lives at plane index (n&3)*1024 + (n>>2);
// beran thread t (owning n = 4t..4t+3) reads g_pk[p][j*1024 + t] -> coalesced.
__device__ unsigned g_pk[4][NP];

__global__ void pack_labels_kernel(const int* __restrict__ c_in) {
    int t = blockIdx.x * blockDim.x + threadIdx.x;
    if (t < NP) {
        const int4* p = (const int4*)(c_in + t * KK);
        int idx = (t & 3) * 1024 + (t >> 2);
        #pragma unroll
        for (int q = 0; q < 4; q++) {
            int4 a = p[q];
            g_pk[q][idx] = (a.x & 255u) | ((a.y & 255u) << 8)
                         | ((a.z & 255u) << 16) | ((a.w & 255u) << 24);
        }
    }
}

// Each block: 1024 threads, TWO samples (b0, b0+1), 4 train points per thread.
__global__ __launch_bounds__(1024, 2) void beran_kernel(
    const float* __restrict__ delta,
    const float* __restrict__ c_p,
    const float* __restrict__ bwp,
    float* __restrict__ out)
{
    __shared__ float s_score[2 * KK * 32];  // 4 KB: [h][k][v] f32
    __shared__ unsigned s_q[KK * 32];       // 2 KB: packed u16 pair per (k,v)
    __shared__ float wsA[32], wsB[32];

    const int tid  = threadIdx.x;
    const int lane = tid & 31;
    const int wid  = tid >> 5;          // 0..31
    const int b0   = blockIdx.x * 2;
    const unsigned FULL = 0xFFFFFFFFu;

    // ---- Phase A: 32 softmax tasks, one per warp: h = wid>>4, k = wid&15 ----
    {
        int h = wid >> 4, k = wid & 15;
        float x = c_p[(k * BB + b0 + h) * 32 + lane];
        float m = x;
        #pragma unroll
        for (int d = 16; d; d >>= 1) m = fmaxf(m, __shfl_xor_sync(FULL, m, d));
        float e = __expf(x - m);
        float s = e;
        #pragma unroll
        for (int d = 16; d; d >>= 1) s += __shfl_xor_sync(FULL, s, d);
        float p = __fdividef(e, s);
        float ssq = p * p;
        #pragma unroll
        for (int d = 16; d; d >>= 1) ssq += __shfl_xor_sync(FULL, ssq, d);
        s_score[h * 512 + k * 32 + lane] = ssq - 2.0f * p + 1.0f;   // in [0,2]
    }

    // early delta load: latency hides under Phase A
    float4 dv = ((const float4*)(delta))[tid];   // delta[4t..4t+3]

    __syncthreads();   // barrier 1

    // ---- pack both samples' score tables into one u32 per (k,v) ----
    if (tid < 512) {
        unsigned qa = (unsigned)__float2int_rn(s_score[tid] * QSCALE);
        unsigned qb = (unsigned)__float2int_rn(s_score[512 + tid] * QSCALE);
        s_q[tid] = qa | (qb << 16);
    }
    __syncthreads();   // barrier 2

    const float bw   = fminf(fmaxf(bwp[0], 0.1f), 10.0f);
    const float nibq = -LOG2E / (bw * QSCALE);   // de-quant + base-2 scale

    // ---- Phase B: gather both samples via ONE shfl per (k, point) ----
    unsigned acc[4] = {0, 0, 0, 0};
    #pragma unroll
    for (int q = 0; q < 4; q++) {
        unsigned sr[4];
        #pragma unroll
        for (int kk = 0; kk < 4; kk++) sr[kk] = s_q[(q * 4 + kk) * 32 + lane];
        #pragma unroll
        for (int j = 0; j < 4; j++) {
            unsigned pk = g_pk[q][j * 1024 + tid];
            unsigned a = acc[j];
            a += (unsigned)__shfl_sync(FULL, (int)sr[0], (int)pk);
            a += (unsigned)__shfl_sync(FULL, (int)sr[1], (int)(pk >> 8));
            a += (unsigned)__shfl_sync(FULL, (int)sr[2], (int)(pk >> 16));
            a += (unsigned)__shfl_sync(FULL, (int)sr[3], (int)(pk >> 24));
            acc[j] = a;
        }
    }
    // unpack exact integer metrics -> w values
    float oa[4], ob[4];
    #pragma unroll
    for (int j = 0; j < 4; j++) {
        float mA = __uint2float_rn(acc[j] & 0xFFFFu);
        float mB = __uint2float_rn(acc[j] >> 16);
        oa[j] = exp2f(mA * nibq);
        ob[j] = exp2f(mB * nibq);
    }

    // ---- Phase C: scan #1 (cumsum of w) ----
    #pragma unroll
    for (int j = 1; j < 4; j++) { oa[j] += oa[j - 1]; ob[j] += ob[j - 1]; }

    float totA = oa[3], totB = ob[3];
    float tiA = totA, tiB = totB;
    #pragma unroll
    for (int d = 1; d < 32; d <<= 1) {
        float ua = __shfl_up_sync(FULL, tiA, d);
        float ub = __shfl_up_sync(FULL, tiB, d);
        if (lane >= d) { tiA += ua; tiB += ub; }
    }
    if (lane == 31) { wsA[wid] = tiA; wsB[wid] = tiB; }
    __syncthreads();   // barrier 3

    // redundant partial-scan: every warp scans the 32 partials itself
    float off1A, off1B, sA, sB;
    {
        float vA = wsA[lane], vB = wsB[lane];
        float viA = vA, viB = vB;
        #pragma unroll
        for (int d = 1; d < 32; d <<= 1) {
            float uA = __shfl_up_sync(FULL, viA, d);
            float uB = __shfl_up_sync(FULL, viB, d);
            if (lane >= d) { viA += uA; viB += uB; }
        }
        float eA = __shfl_sync(FULL, viA, wid - 1);   // wraps for wid=0; masked below
        float eB = __shfl_sync(FULL, viB, wid - 1);
        if (wid == 0) { eA = 0.0f; eB = 0.0f; }
        sA = __shfl_sync(FULL, viA, 31);
        sB = __shfl_sync(FULL, viB, 31);
        off1A = eA + (tiA - totA);
        off1B = eB + (tiB - totB);
    }
    const float tolA = (sA < EPSF) ? 3.0e38f : TOLF * sA;
    const float tolB = (sB < EPSF) ? 3.0e38f : TOLF * sB;

    // ---- Phase D: xi = log2(t_prev/t) on unnormalized residuals (R9 form) ----
    float tot2A = 0.0f, tot2B = 0.0f;
    {
        float tpA = sA - off1A, tpB = sB - off1B;
        #pragma unroll
        for (int j = 0; j < 4; j++) {
            float dl = (j == 0) ? dv.x : (j == 1) ? dv.y : (j == 2) ? dv.z : dv.w;
            float tA = sA - (off1A + oa[j]);
            float tB = sB - (off1B + ob[j]);
            bool badA = (fabsf(tA) <= tolA) || (fabsf(tpA) <= tolA);
            bool badB = (fabsf(tB) <= tolB) || (fabsf(tpB) <= tolB);
            float xiA = badA ? 0.0f : __log2f(__fdividef(tpA, tA));
            float xiB = badB ? 0.0f : __log2f(__fdividef(tpB, tB));
            float vA = dl * xiA, vB = dl * xiB;
            tot2A += vA; tot2B += vB;
            oa[j] = vA; ob[j] = vB;       // o[] now delta*xi (log2 units)
            tpA = tA; tpB = tB;
        }
    }
    #pragma unroll
    for (int j = 1; j < 4; j++) { oa[j] += oa[j - 1]; ob[j] += ob[j - 1]; }

    // ---- Phase E: scan #2 (hazards, log2 units) ----
    float ti2A = tot2A, ti2B = tot2B;
    #pragma unroll
    for (int d = 1; d < 32; d <<= 1) {
        float ua = __shfl_up_sync(FULL, ti2A, d);
        float ub = __shfl_up_sync(FULL, ti2B, d);
        if (lane >= d) { ti2A += ua; ti2B += ub; }
    }
    __syncthreads();   // barrier 4: redundant scan-1 reads of wsA/wsB done
    if (lane == 31) { wsA[wid] = ti2A; wsB[wid] = ti2B; }
    __syncthreads();   // barrier 5

    float off2A, off2B, g2A, g2B;
    {
        float vA = wsA[lane], vB = wsB[lane];
        float viA = vA, viB = vB;
        #pragma unroll
        for (int d = 1; d < 32; d <<= 1) {
            float uA = __shfl_up_sync(FULL, viA, d);
            float uB = __shfl_up_sync(FULL, viB, d);
            if (lane >= d) { viA += uA; viB += uB; }
        }
        float eA = __shfl_sync(FULL, viA, wid - 1);
        float eB = __shfl_sync(FULL, viB, wid - 1);
        if (wid == 0) { eA = 0.0f; eB = 0.0f; }
        g2A = __shfl_sync(FULL, viA, 31);
        g2B = __shfl_sync(FULL, viB, 31);
        off2A = eA + (ti2A - tot2A);
        off2B = eB + (ti2B - tot2B);
    }

    // s2 telescopes: sum(surv_steps) = 1 - surv[N-1]; surv = exp2(-hz2)
    const float s2A = 1.0f - exp2f(-g2A);
    const float s2B = 1.0f - exp2f(-g2B);
    const float inv2A = (s2A < EPSF) ? 0.0f : 1.0f / s2A;
    const float inv2B = (s2B < EPSF) ? 0.0f : 1.0f / s2B;
    float prevA = (tid == 0) ? 1.0f : exp2f(-off2A);
    float prevB = (tid == 0) ? 1.0f : exp2f(-off2B);

    // ---- Phase F: surv (write), then steps in place ----
    #pragma unroll
    for (int j = 0; j < 4; j++) {
        oa[j] = exp2f(-(oa[j] + off2A));
        ob[j] = exp2f(-(ob[j] + off2B));
    }
    {
        float4* opA = (float4*)(out + (size_t)b0 * NP) + tid;
        float4* opB = (float4*)(out + (size_t)(b0 + 1) * NP) + tid;
        opA[0] = make_float4(oa[0], oa[1], oa[2], oa[3]);
        opB[0] = make_float4(ob[0], ob[1], ob[2], ob[3]);
    }
    #pragma unroll
    for (int j = 0; j < 4; j++) {
        float sa = oa[j], sb = ob[j];
        oa[j] = (prevA - sa) * inv2A;
        ob[j] = (prevB - sb) * inv2B;
        prevA = sa; prevB = sb;
    }
    {
        float4* opA = (float4*)(out + (size_t)BB * NP + (size_t)b0 * NP) + tid;
        float4* opB = (float4*)(out + (size_t)BB * NP + (size_t)(b0 + 1) * NP) + tid;
        opA[0] = make_float4(oa[0], oa[1], oa[2], oa[3]);
        opB[0] = make_float4(ob[0], ob[1], ob[2], ob[3]);
    }
}

extern "C" void kernel_launch(void* const* d_in, const int* in_sizes, int n_in,
                              void* d_out, int out_size) {
    const int*   c_in  = (const int*)d_in[0];
    const float* delta = (const float*)d_in[1];
    const float* c_p   = (const float*)d_in[2];
    const float* bwp   = (const float*)d_in[3];
    float* out = (float*)d_out;

    pack_labels_kernel<<<32, 128>>>(c_in);
    beran_kernel<<<BB / 2, 1024>>>(delta, c_p, bwp, out);
}

// round 12
// speedup vs baseline: 1.1366x; 1.0152x over previous
#include <cuda_runtime.h>
#include <cstdint>

#define KK 16
#define BB 512
#define NP 4096
#define EPSF 1e-13f
#define TOLF 1.001e-5f       // np.isclose to 1.0: rtol(1e-5)*1.0 + atol(1e-8)
#define LOG2E 1.4426950408889634f
#define QSCALE 2047.0f       // fixed-point scale; 16*2*2047 = 65504 < 2^16 (no carry)

// labels split into 4 planes; plane p holds concepts 4p..4p+3 (one byte each).
// train point n lives at plane index (n&3)*1024 + (n>>2);
// beran thread t (owning n = 4t..4t+3) reads g_pk[p][j*1024 + t] -> coalesced.
__device__ unsigned g_pk[4][NP];

__global__ void pack_labels_kernel(const int* __restrict__ c_in) {
    int t = blockIdx.x * blockDim.x + threadIdx.x;
    if (t < NP) {
        const int4* p = (const int4*)(c_in + t * KK);
        int idx = (t & 3) * 1024 + (t >> 2);
        #pragma unroll
        for (int q = 0; q < 4; q++) {
            int4 a = p[q];
            g_pk[q][idx] = (a.x & 255u) | ((a.y & 255u) << 8)
                         | ((a.z & 255u) << 16) | ((a.w & 255u) << 24);
        }
    }
}

// Each block: 1024 threads, TWO samples (b0, b0+1), 4 train points per thread.
__global__ __launch_bounds__(1024, 2) void beran_kernel(
    const float* __restrict__ delta,
    const float* __restrict__ c_p,
    const float* __restrict__ bwp,
    float* __restrict__ out)
{
    __shared__ float s_score[2 * KK * 32];  // 4 KB: [h][k][v] f32
    __shared__ unsigned s_q[KK * 32];       // 2 KB: packed u16 pair per (k,v)
    __shared__ float wsA[32], wsB[32];

    const int tid  = threadIdx.x;
    const int lane = tid & 31;
    const int wid  = tid >> 5;          // 0..31
    const int b0   = blockIdx.x * 2;
    const unsigned FULL = 0xFFFFFFFFu;

    // ---- Phase A: 32 softmax tasks, one per warp: h = wid>>4, k = wid&15 ----
    {
        int h = wid >> 4, k = wid & 15;
        float x = c_p[(k * BB + b0 + h) * 32 + lane];
        float m = x;
        #pragma unroll
        for (int d = 16; d; d >>= 1) m = fmaxf(m, __shfl_xor_sync(FULL, m, d));
        float e = __expf(x - m);
        float s = e;
        #pragma unroll
        for (int d = 16; d; d >>= 1) s += __shfl_xor_sync(FULL, s, d);
        float p = __fdividef(e, s);
        float ssq = p * p;
        #pragma unroll
        for (int d = 16; d; d >>= 1) ssq += __shfl_xor_sync(FULL, ssq, d);
        s_score[h * 512 + k * 32 + lane] = ssq - 2.0f * p + 1.0f;   // in [0,2]
    }

    // early delta load: latency hides under Phase A
    float4 dv = ((const float4*)(delta))[tid];   // delta[4t..4t+3]

    __syncthreads();   // barrier 1

    // ---- pack both samples' score tables into one u32 per (k,v) ----
    if (tid < 512) {
        unsigned qa = (unsigned)__float2int_rn(s_score[tid] * QSCALE);
        unsigned qb = (unsigned)__float2int_rn(s_score[512 + tid] * QSCALE);
        s_q[tid] = qa | (qb << 16);
    }
    __syncthreads();   // barrier 2

    const float bw   = fminf(fmaxf(bwp[0], 0.1f), 10.0f);
    const float nibq = -LOG2E / (bw * QSCALE);   // de-quant + base-2 scale

    // ---- Phase B: gather both samples via ONE shfl per (k, point) ----
    unsigned acc[4] = {0, 0, 0, 0};
    #pragma unroll
    for (int q = 0; q < 4; q++) {
        unsigned sr[4];
        #pragma unroll
        for (int kk = 0; kk < 4; kk++) sr[kk] = s_q[(q * 4 + kk) * 32 + lane];
        #pragma unroll
        for (int j = 0; j < 4; j++) {
            unsigned pk = g_pk[q][j * 1024 + tid];
            unsigned a = acc[j];
            a += (unsigned)__shfl_sync(FULL, (int)sr[0], (int)pk);
            a += (unsigned)__shfl_sync(FULL, (int)sr[1], (int)(pk >> 8));
            a += (unsigned)__shfl_sync(FULL, (int)sr[2], (int)(pk >> 16));
            a += (unsigned)__shfl_sync(FULL, (int)sr[3], (int)(pk >> 24));
            acc[j] = a;
        }
    }
    // unpack exact integer metrics -> w values
    float oa[4], ob[4];
    #pragma unroll
    for (int j = 0; j < 4; j++) {
        float mA = __uint2float_rn(acc[j] & 0xFFFFu);
        float mB = __uint2float_rn(acc[j] >> 16);
        oa[j] = exp2f(mA * nibq);
        ob[j] = exp2f(mB * nibq);
    }

    // ---- Phase C: scan #1 (cumsum of w) ----
    #pragma unroll
    for (int j = 1; j < 4; j++) { oa[j] += oa[j - 1]; ob[j] += ob[j - 1]; }

    float totA = oa[3], totB = ob[3];
    float tiA = totA, tiB = totB;
    #pragma unroll
    for (int d = 1; d < 32; d <<= 1) {
        float ua = __shfl_up_sync(FULL, tiA, d);
        float ub = __shfl_up_sync(FULL, tiB, d);
        if (lane >= d) { tiA += ua; tiB += ub; }
    }
    if (lane == 31) { wsA[wid] = tiA; wsB[wid] = tiB; }
    __syncthreads();   // barrier 3

    // redundant partial-scan (sum): every warp scans the 32 partials itself
    float off1A, off1B, sA, sB;
    {
        float vA = wsA[lane], vB = wsB[lane];
        float viA = vA, viB = vB;
        #pragma unroll
        for (int d = 1; d < 32; d <<= 1) {
            float uA = __shfl_up_sync(FULL, viA, d);
            float uB = __shfl_up_sync(FULL, viB, d);
            if (lane >= d) { viA += uA; viB += uB; }
        }
        float eA = __shfl_sync(FULL, viA, wid - 1);   // wraps for wid=0; masked below
        float eB = __shfl_sync(FULL, viB, wid - 1);
        if (wid == 0) { eA = 0.0f; eB = 0.0f; }
        sA = __shfl_sync(FULL, viA, 31);
        sB = __shfl_sync(FULL, viB, 31);
        off1A = eA + (tiA - totA);
        off1B = eB + (tiB - totB);
    }
    const float tolA = (sA < EPSF) ? 3.0e38f : TOLF * sA;
    const float tolB = (sB < EPSF) ? 3.0e38f : TOLF * sB;

    // ---- Phase D: survival RATIOS r = (t/tp)^delta, local inclusive product ----
    // exp(-delta*xi) = (t/tp)^delta ; bad guard -> ratio 1 (xi = 0)
    {
        float tpA = sA - off1A, tpB = sB - off1B;
        float prA = 1.0f, prB = 1.0f;
        #pragma unroll
        for (int j = 0; j < 4; j++) {
            float dl = (j == 0) ? dv.x : (j == 1) ? dv.y : (j == 2) ? dv.z : dv.w;
            float tA = sA - (off1A + oa[j]);
            float tB = sB - (off1B + ob[j]);
            bool useA = (dl != 0.0f) && !((fabsf(tA) <= tolA) || (fabsf(tpA) <= tolA));
            bool useB = (dl != 0.0f) && !((fabsf(tB) <= tolB) || (fabsf(tpB) <= tolB));
            float rA = useA ? __fdividef(tA, tpA) : 1.0f;
            float rB = useB ? __fdividef(tB, tpB) : 1.0f;
            prA *= rA; prB *= rB;
            oa[j] = prA; ob[j] = prB;     // o[] now local inclusive product
            tpA = tA; tpB = tB;
        }
    }
    const float totPA = oa[3], totPB = ob[3];

    // ---- Phase E: product-scan of thread products ----
    float tiPA = totPA, tiPB = totPB;
    #pragma unroll
    for (int d = 1; d < 32; d <<= 1) {
        float ua = __shfl_up_sync(FULL, tiPA, d);
        float ub = __shfl_up_sync(FULL, tiPB, d);
        if (lane >= d) { tiPA *= ua; tiPB *= ub; }
    }
    // exclusive product within warp
    float exPA = __shfl_up_sync(FULL, tiPA, 1);
    float exPB = __shfl_up_sync(FULL, tiPB, 1);
    if (lane == 0) { exPA = 1.0f; exPB = 1.0f; }

    __syncthreads();   // barrier 4: sum-scan reads of wsA/wsB complete
    if (lane == 31) { wsA[wid] = tiPA; wsB[wid] = tiPB; }
    __syncthreads();   // barrier 5

    float off2A, off2B, g2A, g2B;
    {
        float vA = wsA[lane], vB = wsB[lane];
        float viA = vA, viB = vB;
        #pragma unroll
        for (int d = 1; d < 32; d <<= 1) {
            float uA = __shfl_up_sync(FULL, viA, d);
            float uB = __shfl_up_sync(FULL, viB, d);
            if (lane >= d) { viA *= uA; viB *= uB; }
        }
        float eA = __shfl_sync(FULL, viA, wid - 1);
        float eB = __shfl_sync(FULL, viB, wid - 1);
        if (wid == 0) { eA = 1.0f; eB = 1.0f; }
        g2A = __shfl_sync(FULL, viA, 31);     // grand product = surv[N-1]
        g2B = __shfl_sync(FULL, viB, 31);
        off2A = eA * exPA;                    // product of all ratios before my chunk
        off2B = eB * exPB;
    }

    // s2 = sum(surv_steps) = 1 - surv[N-1]
    const float s2A = 1.0f - g2A;
    const float s2B = 1.0f - g2B;
    const float inv2A = (s2A < EPSF) ? 0.0f : 1.0f / s2A;
    const float inv2B = (s2B < EPSF) ? 0.0f : 1.0f / s2B;
    float prevA = (tid == 0) ? 1.0f : off2A;  // surv[4t-1] = exclusive product
    float prevB = (tid == 0) ? 1.0f : off2B;

    // ---- Phase F: surv = off2 * local product (no exp!), then steps ----
    #pragma unroll
    for (int j = 0; j < 4; j++) {
        oa[j] *= off2A;
        ob[j] *= off2B;
    }
    {
        float4* opA = (float4*)(out + (size_t)b0 * NP) + tid;
        float4* opB = (float4*)(out + (size_t)(b0 + 1) * NP) + tid;
        opA[0] = make_float4(oa[0], oa[1], oa[2], oa[3]);
        opB[0] = make_float4(ob[0], ob[1], ob[2], ob[3]);
    }
    #pragma unroll
    for (int j = 0; j < 4; j++) {
        float sa = oa[j], sb = ob[j];
        oa[j] = (prevA - sa) * inv2A;
        ob[j] = (prevB - sb) * inv2B;
        prevA = sa; prevB = sb;
    }
    {
        float4* opA = (float4*)(out + (size_t)BB * NP + (size_t)b0 * NP) + tid;
        float4* opB = (float4*)(out + (size_t)BB * NP + (size_t)(b0 + 1) * NP) + tid;
        opA[0] = make_float4(oa[0], oa[1], oa[2], oa[3]);
        opB[0] = make_float4(ob[0], ob[1], ob[2], ob[3]);
    }
}

extern "C" void kernel_launch(void* const* d_in, const int* in_sizes, int n_in,
                              void* d_out, int out_size) {
    const int*   c_in  = (const int*)d_in[0];
    const float* delta = (const float*)d_in[1];
    const float* c_p   = (const float*)d_in[2];
    const float* bwp   = (const float*)d_in[3];
    float* out = (float*)d_out;

    pack_labels_kernel<<<32, 128>>>(c_in);
    beran_kernel<<<BB / 2, 1024>>>(delta, c_p, bwp, out);
}